// round 8
// baseline (speedup 1.0000x reference)
#include <cuda_runtime.h>
#include <cuda_bf16.h>
#include <cstdint>

// MoE dense 8-expert: D_IN=6, H=32, D_OUT=2, B=1M, fp32.
// R8 = R7 (both layers mma.sync bf16 3-split, C-operand bias folding, packed
// gate) with occupancy raised 2 -> 3 CTAs/SM (139 regs x 3 CTAs fits; extra
// warps fill the measured 50% tensor-pipe stall slots).

#define ED 8
#define DI 6
#define HH 32
#define DO 2

typedef unsigned long long u64;
typedef unsigned int u32;

// ---- scalar helpers ----
__device__ __forceinline__ void ffma2_acc(u64& acc, u64 a, u64 b) {
    asm("fma.rn.f32x2 %0, %1, %2, %0;" : "+l"(acc) : "l"(a), "l"(b));
}
__device__ __forceinline__ u64 pack_dup(float v) {
    u64 r; asm("mov.b64 %0, {%1, %1};" : "=l"(r) : "r"(__float_as_uint(v))); return r;
}
__device__ __forceinline__ float2 unpack2(u64 v) {
    float2 f; asm("mov.b64 {%0, %1}, %2;" : "=f"(f.x), "=f"(f.y) : "l"(v)); return f;
}
__device__ __forceinline__ u32 bf16x2_of(float lo_e, float hi_e) {
    u32 r; asm("cvt.rn.bf16x2.f32 %0, %1, %2;" : "=r"(r) : "f"(hi_e), "f"(lo_e)); return r;
}
__device__ __forceinline__ float bflo(u32 p) { return __uint_as_float(p << 16); }
__device__ __forceinline__ float bfhi(u32 p) { return __uint_as_float(p & 0xffff0000u); }

// ---- MMA helpers ----
__device__ __forceinline__ void mma_bf16(float& d0, float& d1, float& d2, float& d3,
                                         u32 a0, u32 a1, u32 a2, u32 a3,
                                         u32 b0, u32 b1) {
    asm("mma.sync.aligned.m16n8k16.row.col.f32.bf16.bf16.f32 "
        "{%0,%1,%2,%3}, {%4,%5,%6,%7}, {%8,%9}, {%0,%1,%2,%3};"
        : "+f"(d0), "+f"(d1), "+f"(d2), "+f"(d3)
        : "r"(a0), "r"(a1), "r"(a2), "r"(a3), "r"(b0), "r"(b1));
}
__device__ __forceinline__ void mma_bf16_c(float& d0, float& d1, float& d2, float& d3,
                                           u32 a0, u32 a1, u32 a2, u32 a3,
                                           u32 b0, u32 b1,
                                           float c0, float c1, float c2, float c3) {
    asm("mma.sync.aligned.m16n8k16.row.col.f32.bf16.bf16.f32 "
        "{%0,%1,%2,%3}, {%4,%5,%6,%7}, {%8,%9}, {%10,%11,%12,%13};"
        : "=f"(d0), "=f"(d1), "=f"(d2), "=f"(d3)
        : "r"(a0), "r"(a1), "r"(a2), "r"(a3), "r"(b0), "r"(b1),
          "f"(c0), "f"(c1), "f"(c2), "f"(c3));
}
__device__ __forceinline__ void mma_bf16_k8(float& d0, float& d1, float& d2, float& d3,
                                            u32 a0, u32 a1, u32 b0) {
    asm("mma.sync.aligned.m16n8k8.row.col.f32.bf16.bf16.f32 "
        "{%0,%1,%2,%3}, {%4,%5}, {%6}, {%0,%1,%2,%3};"
        : "+f"(d0), "+f"(d1), "+f"(d2), "+f"(d3)
        : "r"(a0), "r"(a1), "r"(b0));
}
__device__ __forceinline__ void mma_bf16_k8_c(float& d0, float& d1, float& d2, float& d3,
                                              u32 a0, u32 a1, u32 b0,
                                              float c0, float c1, float c2, float c3) {
    asm("mma.sync.aligned.m16n8k8.row.col.f32.bf16.bf16.f32 "
        "{%0,%1,%2,%3}, {%4,%5}, {%6}, {%7,%8,%9,%10};"
        : "=f"(d0), "=f"(d1), "=f"(d2), "=f"(d3)
        : "r"(a0), "r"(a1), "r"(b0),
          "f"(c0), "f"(c1), "f"(c2), "f"(c3));
}

__global__ __launch_bounds__(128, 3)
void moe_mma_kernel(const float* __restrict__ gx,
                    const float* __restrict__ gW1, const float* __restrict__ gb1,
                    const float* __restrict__ gW2, const float* __restrict__ gb2,
                    const float* __restrict__ gW3, const float* __restrict__ gb3,
                    const float* __restrict__ gWg1, const float* __restrict__ gbg1,
                    const float* __restrict__ gWg2, const float* __restrict__ gbg2,
                    float* __restrict__ gout, int B, int NT)
{
    __shared__ __align__(16) float sx[4 * 192];               // per-warp x tiles
    __shared__ __align__(16) char  sBfrag[ED * 8 * 32 * 16];  // layer-2 W2 frags (hi|lo)
    __shared__ __align__(16) char  sB1frag[ED * 2 * 32 * 16]; // layer-1 W1 frags, b1 @k=6
    __shared__ __align__(16) float sb2[ED * HH];
    __shared__ __align__(16) float sW3[ED * HH * DO];
    __shared__ __align__(16) float sb3[ED * DO];
    __shared__ __align__(16) float sWg1[DI * HH];
    __shared__ __align__(16) float sbg1[HH];
    __shared__ __align__(16) float sWg2[HH * ED];
    __shared__ __align__(16) float sbg2[ED];

    const int tid  = threadIdx.x;
    const int w    = tid >> 5;
    const int lane = tid & 31;
    const int g    = lane >> 2;   // groupID
    const int q    = lane & 3;    // threadID in group

    // ---- stage small weights ----
    for (int i = tid; i < ED * HH;      i += 128) sb2[i]  = gb2[i];
    for (int i = tid; i < ED * HH * DO; i += 128) sW3[i]  = gW3[i];
    for (int i = tid; i < ED * DO;      i += 128) sb3[i]  = gb3[i];
    for (int i = tid; i < DI * HH;      i += 128) sWg1[i] = gWg1[i];
    for (int i = tid; i < HH;           i += 128) sbg1[i] = gbg1[i];
    for (int i = tid; i < HH * ED;      i += 128) sWg2[i] = gWg2[i];
    for (int i = tid; i < ED;           i += 128) sbg2[i] = gbg2[i];

    // ---- precompute per-lane B fragments ----
    for (int e = w * 2; e < w * 2 + 2; e++) {
        // layer-2 (W2, k16 frags: 4 hi chunks + 4 lo chunks)
        #pragma unroll
        for (int c = 0; c < 4; c++) {
            const int kf = c >> 1, nfh = c & 1;
            u32 hi4[4], lo4[4];
            #pragma unroll
            for (int p = 0; p < 2; p++) {
                const int n  = (nfh * 2 + p) * 8 + g;
                const int k0 = kf * 16 + 2 * q;
                const float w00 = gW2[e * 1024 + (k0    ) * 32 + n];
                const float w01 = gW2[e * 1024 + (k0 + 1) * 32 + n];
                const float w10 = gW2[e * 1024 + (k0 + 8) * 32 + n];
                const float w11 = gW2[e * 1024 + (k0 + 9) * 32 + n];
                const u32 h0 = bf16x2_of(w00, w01);
                const u32 h1 = bf16x2_of(w10, w11);
                hi4[p * 2 + 0] = h0;
                hi4[p * 2 + 1] = h1;
                lo4[p * 2 + 0] = bf16x2_of(w00 - bflo(h0), w01 - bfhi(h0));
                lo4[p * 2 + 1] = bf16x2_of(w10 - bflo(h1), w11 - bfhi(h1));
            }
            *(uint4*)(sBfrag + ((e * 8 + c    ) * 32 + lane) * 16) = make_uint4(hi4[0], hi4[1], hi4[2], hi4[3]);
            *(uint4*)(sBfrag + ((e * 8 + c + 4) * 32 + lane) * 16) = make_uint4(lo4[0], lo4[1], lo4[2], lo4[3]);
        }
        // layer-1 (W1, k8 frags; q==3 carries b1 at k=6, 0 at k=7)
        {
            u32 hi4[4], lo4[4];
            #pragma unroll
            for (int nf = 0; nf < 4; nf++) {
                const int n = nf * 8 + g;
                float w0, w1;
                if (q < 3) {
                    w0 = gW1[e * 192 + (2 * q    ) * 32 + n];
                    w1 = gW1[e * 192 + (2 * q + 1) * 32 + n];
                } else {
                    w0 = gb1[e * 32 + n];
                    w1 = 0.0f;
                }
                const u32 h = bf16x2_of(w0, w1);
                hi4[nf] = h;
                lo4[nf] = bf16x2_of(w0 - bflo(h), w1 - bfhi(h));
            }
            *(uint4*)(sB1frag + ((e * 2 + 0) * 32 + lane) * 16) = make_uint4(hi4[0], hi4[1], hi4[2], hi4[3]);
            *(uint4*)(sB1frag + ((e * 2 + 1) * 32 + lane) * 16) = make_uint4(lo4[0], lo4[1], lo4[2], lo4[3]);
        }
    }
    __syncthreads();

    const int lim6 = B * DI;
    const float fz = 0.0f;

    // ---- persistent per-warp tile loop (32 tokens per warp) ----
    for (int tile = blockIdx.x; tile < NT; tile += gridDim.x) {
        const int base = tile * 128 + w * 32;
        float* sxw = sx + w * 192;
        #pragma unroll
        for (int i = 0; i < 6; i++) {
            const int idx = base * DI + i * 32 + lane;
            sxw[i * 32 + lane] = (idx < lim6) ? gx[idx] : 0.0f;
        }
        __syncwarp();

        // ---- build x A-fragments (k8), shared by all experts; k=6 slot = 1.0 ----
        u32 xhi[2][2], xlo[2][2];
        #pragma unroll
        for (int mf = 0; mf < 2; mf++) {
            const int r0 = 16 * mf + g, r1 = r0 + 8;
            float v00, v01, v10, v11;
            if (q < 3) {
                v00 = sxw[r0 * DI + 2 * q]; v01 = sxw[r0 * DI + 2 * q + 1];
                v10 = sxw[r1 * DI + 2 * q]; v11 = sxw[r1 * DI + 2 * q + 1];
            } else {
                v00 = 1.0f; v01 = 0.0f; v10 = 1.0f; v11 = 0.0f;
            }
            const u32 h0 = bf16x2_of(v00, v01);
            const u32 h1 = bf16x2_of(v10, v11);
            xhi[mf][0] = h0; xhi[mf][1] = h1;
            xlo[mf][0] = bf16x2_of(v00 - bflo(h0), v01 - bfhi(h0));
            xlo[mf][1] = bf16x2_of(v10 - bflo(h1), v11 - bfhi(h1));
        }

        // ---- gate for token (g + 8q): packed FFMA2 ----
        float gg[ED];
        {
            const float* xg = sxw + (g + 8 * q) * DI;
            u64 gacc[HH / 2];
            const u64* bg1p = (const u64*)sbg1;
            #pragma unroll
            for (int i = 0; i < HH / 2; i++) gacc[i] = bg1p[i];
            #pragma unroll
            for (int d = 0; d < DI; d++) {
                const u64 xd = pack_dup(xg[d]);
                const u64* wr = (const u64*)(sWg1 + d * HH);
                #pragma unroll
                for (int i = 0; i < HH / 2; i++) ffma2_acc(gacc[i], xd, wr[i]);
            }
            u64 lacc[ED / 2];
            const u64* bg2p = (const u64*)sbg2;
            #pragma unroll
            for (int i = 0; i < ED / 2; i++) lacc[i] = bg2p[i];
            #pragma unroll
            for (int i = 0; i < HH / 2; i++) {
                const float2 t = unpack2(gacc[i]);
                const u64 hj0 = pack_dup(fmaxf(t.x, 0.0f));
                const u64 hj1 = pack_dup(fmaxf(t.y, 0.0f));
                const u64* wr0 = (const u64*)(sWg2 + (2 * i    ) * ED);
                const u64* wr1 = (const u64*)(sWg2 + (2 * i + 1) * ED);
                #pragma unroll
                for (int k2 = 0; k2 < ED / 2; k2++) {
                    ffma2_acc(lacc[k2], hj0, wr0[k2]);
                    ffma2_acc(lacc[k2], hj1, wr1[k2]);
                }
            }
            float lg[ED];
            #pragma unroll
            for (int i = 0; i < ED / 2; i++) {
                const float2 t = unpack2(lacc[i]);
                lg[2 * i] = t.x; lg[2 * i + 1] = t.y;
            }
            float mx = lg[0];
            #pragma unroll
            for (int e = 1; e < ED; e++) mx = fmaxf(mx, lg[e]);
            float s = 0.0f;
            #pragma unroll
            for (int e = 0; e < ED; e++) { lg[e] = __expf(lg[e] - mx); s += lg[e]; }
            const float inv = 1.0f / s;
            #pragma unroll
            for (int e = 0; e < ED; e++) gg[e] = lg[e] * inv;
        }

        float2 oP[4];
        #pragma unroll
        for (int m = 0; m < 4; m++) oP[m] = make_float2(0.0f, 0.0f);

        // ---- experts ----
        #pragma unroll
        for (int e = 0; e < ED; e++) {
            // layer 1 via mma.k8: h1 = x @ W1[e] (+b1 via k=6 slot); C = zeros
            const uint4 bh4 = *(const uint4*)(sB1frag + ((e * 2 + 0) * 32 + lane) * 16);
            const uint4 bl4 = *(const uint4*)(sB1frag + ((e * 2 + 1) * 32 + lane) * 16);
            float h1d[2][4][4];
            #pragma unroll
            for (int nf = 0; nf < 4; nf++) {
                const u32 bh = (nf == 0) ? bh4.x : (nf == 1) ? bh4.y : (nf == 2) ? bh4.z : bh4.w;
                const u32 bl = (nf == 0) ? bl4.x : (nf == 1) ? bl4.y : (nf == 2) ? bl4.z : bl4.w;
                #pragma unroll
                for (int mf = 0; mf < 2; mf++) {
                    mma_bf16_k8_c(h1d[mf][nf][0], h1d[mf][nf][1], h1d[mf][nf][2], h1d[mf][nf][3],
                                  xhi[mf][0], xhi[mf][1], bh, fz, fz, fz, fz);
                    mma_bf16_k8(h1d[mf][nf][0], h1d[mf][nf][1], h1d[mf][nf][2], h1d[mf][nf][3],
                                xlo[mf][0], xlo[mf][1], bh);
                    mma_bf16_k8(h1d[mf][nf][0], h1d[mf][nf][1], h1d[mf][nf][2], h1d[mf][nf][3],
                                xhi[mf][0], xhi[mf][1], bl);
                }
            }

            // relu + bf16 split: D-frags -> layer-2 A-frags (no reshuffle)
            u32 ahi[2][2][4], alo[2][2][4];
            #pragma unroll
            for (int mf = 0; mf < 2; mf++) {
                #pragma unroll
                for (int kf = 0; kf < 2; kf++) {
                    #pragma unroll
                    for (int half = 0; half < 2; half++) {
                        const int nf = 2 * kf + half;
                        const float f0 = fmaxf(h1d[mf][nf][0], 0.0f);
                        const float f1 = fmaxf(h1d[mf][nf][1], 0.0f);
                        const float f2 = fmaxf(h1d[mf][nf][2], 0.0f);
                        const float f3 = fmaxf(h1d[mf][nf][3], 0.0f);
                        const u32 hA = bf16x2_of(f0, f1);
                        const u32 hB = bf16x2_of(f2, f3);
                        ahi[mf][kf][half * 2 + 0] = hA;
                        ahi[mf][kf][half * 2 + 1] = hB;
                        alo[mf][kf][half * 2 + 0] = bf16x2_of(f0 - bflo(hA), f1 - bfhi(hA));
                        alo[mf][kf][half * 2 + 1] = bf16x2_of(f2 - bflo(hB), f3 - bfhi(hB));
                    }
                }
            }

            // layer-2 B fragments + b2 bias fragments
            uint4 cH[4], cL[4];
            #pragma unroll
            for (int c = 0; c < 4; c++) {
                cH[c] = *(const uint4*)(sBfrag + ((e * 8 + c    ) * 32 + lane) * 16);
                cL[c] = *(const uint4*)(sBfrag + ((e * 8 + c + 4) * 32 + lane) * 16);
            }
            float2 b2p[4];
            #pragma unroll
            for (int nf = 0; nf < 4; nf++) b2p[nf] = *(const float2*)&sb2[e * HH + nf * 8 + 2 * q];

            // layer-2: D = A_hi*B_hi + A_lo*B_hi + A_hi*B_lo, C(first) = b2
            float dd[2][4][4];
            #pragma unroll
            for (int nf = 0; nf < 4; nf++) {
                const uint4 h40 = cH[0 * 2 + (nf >> 1)];
                const uint4 l40 = cL[0 * 2 + (nf >> 1)];
                const uint4 h41 = cH[1 * 2 + (nf >> 1)];
                const uint4 l41 = cL[1 * 2 + (nf >> 1)];
                const u32 b0h0 = (nf & 1) ? h40.z : h40.x;
                const u32 b1h0 = (nf & 1) ? h40.w : h40.y;
                const u32 b0l0 = (nf & 1) ? l40.z : l40.x;
                const u32 b1l0 = (nf & 1) ? l40.w : l40.y;
                const u32 b0h1 = (nf & 1) ? h41.z : h41.x;
                const u32 b1h1 = (nf & 1) ? h41.w : h41.y;
                const u32 b0l1 = (nf & 1) ? l41.z : l41.x;
                const u32 b1l1 = (nf & 1) ? l41.w : l41.y;
                #pragma unroll
                for (int mf = 0; mf < 2; mf++) {
                    mma_bf16_c(dd[mf][nf][0], dd[mf][nf][1], dd[mf][nf][2], dd[mf][nf][3],
                               ahi[mf][0][0], ahi[mf][0][1], ahi[mf][0][2], ahi[mf][0][3],
                               b0h0, b1h0,
                               b2p[nf].x, b2p[nf].y, b2p[nf].x, b2p[nf].y);
                    mma_bf16(dd[mf][nf][0], dd[mf][nf][1], dd[mf][nf][2], dd[mf][nf][3],
                             alo[mf][0][0], alo[mf][0][1], alo[mf][0][2], alo[mf][0][3],
                             b0h0, b1h0);
                    mma_bf16(dd[mf][nf][0], dd[mf][nf][1], dd[mf][nf][2], dd[mf][nf][3],
                             ahi[mf][0][0], ahi[mf][0][1], ahi[mf][0][2], ahi[mf][0][3],
                             b0l0, b1l0);
                    mma_bf16(dd[mf][nf][0], dd[mf][nf][1], dd[mf][nf][2], dd[mf][nf][3],
                             ahi[mf][1][0], ahi[mf][1][1], ahi[mf][1][2], ahi[mf][1][3],
                             b0h1, b1h1);
                    mma_bf16(dd[mf][nf][0], dd[mf][nf][1], dd[mf][nf][2], dd[mf][nf][3],
                             alo[mf][1][0], alo[mf][1][1], alo[mf][1][2], alo[mf][1][3],
                             b0h1, b1h1);
                    mma_bf16(dd[mf][nf][0], dd[mf][nf][1], dd[mf][nf][2], dd[mf][nf][3],
                             ahi[mf][1][0], ahi[mf][1][1], ahi[mf][1][2], ahi[mf][1][3],
                             b0l1, b1l1);
                }
            }

            // epilogue: relu + layer3 + gate-weighted accumulate (b2 already in D)
            float4 w34[4];
            #pragma unroll
            for (int nf = 0; nf < 4; nf++)
                w34[nf] = *(const float4*)&sW3[(e * HH + nf * 8 + 2 * q) * DO];
            const float y0b = sb3[e * DO + 0];
            const float y1b = sb3[e * DO + 1];
            #pragma unroll
            for (int m = 0; m < 4; m++) {
                const int mf = m >> 1, r = m & 1;
                float y0 = y0b, y1 = y1b;
                #pragma unroll
                for (int nf = 0; nf < 4; nf++) {
                    const float ha = fmaxf(dd[mf][nf][r * 2 + 0], 0.0f);
                    const float hb = fmaxf(dd[mf][nf][r * 2 + 1], 0.0f);
                    y0 = fmaf(ha, w34[nf].x, y0);
                    y1 = fmaf(ha, w34[nf].y, y1);
                    y0 = fmaf(hb, w34[nf].z, y0);
                    y1 = fmaf(hb, w34[nf].w, y1);
                }
                const float ge = __shfl_sync(0xffffffffu, gg[e], (lane & 28) + m);
                oP[m].x = fmaf(ge, y0, oP[m].x);
                oP[m].y = fmaf(ge, y1, oP[m].y);
            }
        }

        // ---- quad butterfly reduction, write own token ----
        #pragma unroll
        for (int m = 0; m < 4; m++) {
            #pragma unroll
            for (int o = 1; o <= 2; o <<= 1) {
                oP[m].x += __shfl_xor_sync(0xffffffffu, oP[m].x, o);
                oP[m].y += __shfl_xor_sync(0xffffffffu, oP[m].y, o);
            }
        }
        float2 res = oP[0];
        if (q == 1) res = oP[1];
        if (q == 2) res = oP[2];
        if (q == 3) res = oP[3];
        const int t = base + g + 8 * q;
        if (t < B) ((float2*)gout)[t] = res;
    }
}

extern "C" void kernel_launch(void* const* d_in, const int* in_sizes, int n_in,
                              void* d_out, int out_size)
{
    const float* x   = (const float*)d_in[0];
    const float* W1  = (const float*)d_in[1];
    const float* b1  = (const float*)d_in[2];
    const float* W2  = (const float*)d_in[3];
    const float* b2  = (const float*)d_in[4];
    const float* W3  = (const float*)d_in[5];
    const float* b3  = (const float*)d_in[6];
    const float* Wg1 = (const float*)d_in[7];
    const float* bg1 = (const float*)d_in[8];
    const float* Wg2 = (const float*)d_in[9];
    const float* bg2 = (const float*)d_in[10];
    float* out = (float*)d_out;

    const int B  = in_sizes[0] / DI;
    const int NT = (B + 127) / 128;

    int nsm = 148;
    cudaDeviceGetAttribute(&nsm, cudaDevAttrMultiProcessorCount, 0);
    int grid = 3 * nsm;          // 3 CTAs/SM — fill tensor stall slots
    if (grid > NT) grid = NT;

    moe_mma_kernel<<<grid, 128>>>(x, W1, b1, W2, b2, W3, b3,
                                  Wg1, bg1, Wg2, bg2, out, B, NT);
}

// round 9
// speedup vs baseline: 1.0061x; 1.0061x over previous
#include <cuda_runtime.h>
#include <cuda_bf16.h>
#include <cstdint>

// MoE dense 8-expert: D_IN=6, H=32, D_OUT=2, B=1M, fp32.
// R9 = R7 compute scheme (mma.sync bf16 3-split both layers, C-operand bias)
// with scalar-side cuts: 64 tokens/warp (2 chunks, B-frags amortized),
// gate handoff via smem (no SHFL broadcast), layer-1 repacked as k16+k8
// (duplicated-B trick), expert loop rolled to fit I$.

#define ED 8
#define DI 6
#define HH 32
#define DO 2

typedef unsigned long long u64;
typedef unsigned int u32;

// ---- scalar helpers ----
__device__ __forceinline__ void ffma2_acc(u64& acc, u64 a, u64 b) {
    asm("fma.rn.f32x2 %0, %1, %2, %0;" : "+l"(acc) : "l"(a), "l"(b));
}
__device__ __forceinline__ u64 pack_dup(float v) {
    u64 r; asm("mov.b64 %0, {%1, %1};" : "=l"(r) : "r"(__float_as_uint(v))); return r;
}
__device__ __forceinline__ float2 unpack2(u64 v) {
    float2 f; asm("mov.b64 {%0, %1}, %2;" : "=f"(f.x), "=f"(f.y) : "l"(v)); return f;
}
__device__ __forceinline__ u32 bf16x2_of(float lo_e, float hi_e) {
    u32 r; asm("cvt.rn.bf16x2.f32 %0, %1, %2;" : "=r"(r) : "f"(hi_e), "f"(lo_e)); return r;
}
__device__ __forceinline__ float bflo(u32 p) { return __uint_as_float(p << 16); }
__device__ __forceinline__ float bfhi(u32 p) { return __uint_as_float(p & 0xffff0000u); }

// ---- MMA helpers ----
__device__ __forceinline__ void mma_bf16(float& d0, float& d1, float& d2, float& d3,
                                         u32 a0, u32 a1, u32 a2, u32 a3,
                                         u32 b0, u32 b1) {
    asm("mma.sync.aligned.m16n8k16.row.col.f32.bf16.bf16.f32 "
        "{%0,%1,%2,%3}, {%4,%5,%6,%7}, {%8,%9}, {%0,%1,%2,%3};"
        : "+f"(d0), "+f"(d1), "+f"(d2), "+f"(d3)
        : "r"(a0), "r"(a1), "r"(a2), "r"(a3), "r"(b0), "r"(b1));
}
__device__ __forceinline__ void mma_bf16_c(float& d0, float& d1, float& d2, float& d3,
                                           u32 a0, u32 a1, u32 a2, u32 a3,
                                           u32 b0, u32 b1,
                                           float c0, float c1, float c2, float c3) {
    asm("mma.sync.aligned.m16n8k16.row.col.f32.bf16.bf16.f32 "
        "{%0,%1,%2,%3}, {%4,%5,%6,%7}, {%8,%9}, {%10,%11,%12,%13};"
        : "=f"(d0), "=f"(d1), "=f"(d2), "=f"(d3)
        : "r"(a0), "r"(a1), "r"(a2), "r"(a3), "r"(b0), "r"(b1),
          "f"(c0), "f"(c1), "f"(c2), "f"(c3));
}
__device__ __forceinline__ void mma_bf16_k8(float& d0, float& d1, float& d2, float& d3,
                                            u32 a0, u32 a1, u32 b0) {
    asm("mma.sync.aligned.m16n8k8.row.col.f32.bf16.bf16.f32 "
        "{%0,%1,%2,%3}, {%4,%5}, {%6}, {%0,%1,%2,%3};"
        : "+f"(d0), "+f"(d1), "+f"(d2), "+f"(d3)
        : "r"(a0), "r"(a1), "r"(b0));
}

__global__ __launch_bounds__(128)
void moe_mma_kernel(const float* __restrict__ gx,
                    const float* __restrict__ gW1, const float* __restrict__ gb1,
                    const float* __restrict__ gW2, const float* __restrict__ gb2,
                    const float* __restrict__ gW3, const float* __restrict__ gb3,
                    const float* __restrict__ gWg1, const float* __restrict__ gbg1,
                    const float* __restrict__ gWg2, const float* __restrict__ gbg2,
                    float* __restrict__ gout, int B, int NT)
{
    __shared__ __align__(16) float sx[4 * 384];               // per-warp x (64 tok x 6)
    __shared__ __align__(16) float sgate[4 * ED * 64];        // per-warp gates [e][tok]
    __shared__ __align__(16) char  sBfrag[ED * 8 * 32 * 16];  // layer-2 W2 frags (hi|lo)
    __shared__ __align__(16) char  sB1frag[ED * 2 * 32 * 16]; // layer-1 W1 frags, b1 @k=6
    __shared__ __align__(16) float sb2[ED * HH];
    __shared__ __align__(16) float sW3[ED * HH * DO];
    __shared__ __align__(16) float sb3[ED * DO];
    __shared__ __align__(16) float sWg1[DI * HH];
    __shared__ __align__(16) float sbg1[HH];
    __shared__ __align__(16) float sWg2[HH * ED];
    __shared__ __align__(16) float sbg2[ED];

    const int tid  = threadIdx.x;
    const int w    = tid >> 5;
    const int lane = tid & 31;
    const int g    = lane >> 2;   // groupID
    const int q    = lane & 3;    // threadID in group

    // ---- stage small weights ----
    for (int i = tid; i < ED * HH;      i += 128) sb2[i]  = gb2[i];
    for (int i = tid; i < ED * HH * DO; i += 128) sW3[i]  = gW3[i];
    for (int i = tid; i < ED * DO;      i += 128) sb3[i]  = gb3[i];
    for (int i = tid; i < DI * HH;      i += 128) sWg1[i] = gWg1[i];
    for (int i = tid; i < HH;           i += 128) sbg1[i] = gbg1[i];
    for (int i = tid; i < HH * ED;      i += 128) sWg2[i] = gWg2[i];
    for (int i = tid; i < ED;           i += 128) sbg2[i] = gbg2[i];

    // ---- precompute per-lane B fragments ----
    for (int e = w * 2; e < w * 2 + 2; e++) {
        // layer-2 (W2, k16 frags: 4 hi chunks + 4 lo chunks)
        #pragma unroll
        for (int c = 0; c < 4; c++) {
            const int kf = c >> 1, nfh = c & 1;
            u32 hi4[4], lo4[4];
            #pragma unroll
            for (int p = 0; p < 2; p++) {
                const int n  = (nfh * 2 + p) * 8 + g;
                const int k0 = kf * 16 + 2 * q;
                const float w00 = gW2[e * 1024 + (k0    ) * 32 + n];
                const float w01 = gW2[e * 1024 + (k0 + 1) * 32 + n];
                const float w10 = gW2[e * 1024 + (k0 + 8) * 32 + n];
                const float w11 = gW2[e * 1024 + (k0 + 9) * 32 + n];
                const u32 h0 = bf16x2_of(w00, w01);
                const u32 h1 = bf16x2_of(w10, w11);
                hi4[p * 2 + 0] = h0;
                hi4[p * 2 + 1] = h1;
                lo4[p * 2 + 0] = bf16x2_of(w00 - bflo(h0), w01 - bfhi(h0));
                lo4[p * 2 + 1] = bf16x2_of(w10 - bflo(h1), w11 - bfhi(h1));
            }
            *(uint4*)(sBfrag + ((e * 8 + c    ) * 32 + lane) * 16) = make_uint4(hi4[0], hi4[1], hi4[2], hi4[3]);
            *(uint4*)(sBfrag + ((e * 8 + c + 4) * 32 + lane) * 16) = make_uint4(lo4[0], lo4[1], lo4[2], lo4[3]);
        }
        // layer-1 (W1, k8 frags; q==3 carries b1 at k=6, 0 at k=7)
        {
            u32 hi4[4], lo4[4];
            #pragma unroll
            for (int nf = 0; nf < 4; nf++) {
                const int n = nf * 8 + g;
                float w0, w1;
                if (q < 3) {
                    w0 = gW1[e * 192 + (2 * q    ) * 32 + n];
                    w1 = gW1[e * 192 + (2 * q + 1) * 32 + n];
                } else {
                    w0 = gb1[e * 32 + n];
                    w1 = 0.0f;
                }
                const u32 h = bf16x2_of(w0, w1);
                hi4[nf] = h;
                lo4[nf] = bf16x2_of(w0 - bflo(h), w1 - bfhi(h));
            }
            *(uint4*)(sB1frag + ((e * 2 + 0) * 32 + lane) * 16) = make_uint4(hi4[0], hi4[1], hi4[2], hi4[3]);
            *(uint4*)(sB1frag + ((e * 2 + 1) * 32 + lane) * 16) = make_uint4(lo4[0], lo4[1], lo4[2], lo4[3]);
        }
    }
    __syncthreads();

    const int lim6 = B * DI;
    const float fz = 0.0f;
    float* sxw = sx + w * 384;
    float* sgw = sgate + w * (ED * 64);

    // ---- persistent per-warp tile loop (64 tokens per warp, 256/CTA) ----
    for (int tile = blockIdx.x; tile < NT; tile += gridDim.x) {
        const int base = tile * 256 + w * 64;

        #pragma unroll
        for (int i = 0; i < 12; i++) {
            const int idx = base * DI + i * 32 + lane;
            sxw[i * 32 + lane] = (idx < lim6) ? gx[idx] : 0.0f;
        }
        __syncwarp();

        // ---- x A-fragments for both chunks (k8 layout); q==3 -> 1.0 bias lane ----
        u32 xhi[2][2][2], xlo[2][2][2];   // [chunk][mf][reg]
        #pragma unroll
        for (int c = 0; c < 2; c++) {
            #pragma unroll
            for (int mf = 0; mf < 2; mf++) {
                const int r0 = 32 * c + 16 * mf + g, r1 = r0 + 8;
                float v00, v01, v10, v11;
                if (q < 3) {
                    v00 = sxw[r0 * DI + 2 * q]; v01 = sxw[r0 * DI + 2 * q + 1];
                    v10 = sxw[r1 * DI + 2 * q]; v11 = sxw[r1 * DI + 2 * q + 1];
                } else {
                    v00 = 1.0f; v01 = 0.0f; v10 = 1.0f; v11 = 0.0f;
                }
                const u32 h0 = bf16x2_of(v00, v01);
                const u32 h1 = bf16x2_of(v10, v11);
                xhi[c][mf][0] = h0; xhi[c][mf][1] = h1;
                xlo[c][mf][0] = bf16x2_of(v00 - bflo(h0), v01 - bfhi(h0));
                xlo[c][mf][1] = bf16x2_of(v10 - bflo(h1), v11 - bfhi(h1));
            }
        }

        // ---- gate per chunk (token 32c + g + 8q), packed FFMA2, results -> smem ----
        #pragma unroll
        for (int c = 0; c < 2; c++) {
            const int tc = 32 * c + g + 8 * q;
            const float* xg = sxw + tc * DI;
            u64 gacc[HH / 2];
            const u64* bg1p = (const u64*)sbg1;
            #pragma unroll
            for (int i = 0; i < HH / 2; i++) gacc[i] = bg1p[i];
            #pragma unroll
            for (int d = 0; d < DI; d++) {
                const u64 xd = pack_dup(xg[d]);
                const u64* wr = (const u64*)(sWg1 + d * HH);
                #pragma unroll
                for (int i = 0; i < HH / 2; i++) ffma2_acc(gacc[i], xd, wr[i]);
            }
            u64 lacc[ED / 2];
            const u64* bg2p = (const u64*)sbg2;
            #pragma unroll
            for (int i = 0; i < ED / 2; i++) lacc[i] = bg2p[i];
            #pragma unroll
            for (int i = 0; i < HH / 2; i++) {
                const float2 t = unpack2(gacc[i]);
                const u64 hj0 = pack_dup(fmaxf(t.x, 0.0f));
                const u64 hj1 = pack_dup(fmaxf(t.y, 0.0f));
                const u64* wr0 = (const u64*)(sWg2 + (2 * i    ) * ED);
                const u64* wr1 = (const u64*)(sWg2 + (2 * i + 1) * ED);
                #pragma unroll
                for (int k2 = 0; k2 < ED / 2; k2++) {
                    ffma2_acc(lacc[k2], hj0, wr0[k2]);
                    ffma2_acc(lacc[k2], hj1, wr1[k2]);
                }
            }
            float lg[ED];
            #pragma unroll
            for (int i = 0; i < ED / 2; i++) {
                const float2 t = unpack2(lacc[i]);
                lg[2 * i] = t.x; lg[2 * i + 1] = t.y;
            }
            float mx = lg[0];
            #pragma unroll
            for (int e = 1; e < ED; e++) mx = fmaxf(mx, lg[e]);
            float s = 0.0f;
            #pragma unroll
            for (int e = 0; e < ED; e++) { lg[e] = __expf(lg[e] - mx); s += lg[e]; }
            const float inv = 1.0f / s;
            #pragma unroll
            for (int e = 0; e < ED; e++) sgw[e * 64 + tc] = lg[e] * inv;
        }
        __syncwarp();

        float2 oP[2][4];
        #pragma unroll
        for (int c = 0; c < 2; c++)
            #pragma unroll
            for (int m = 0; m < 4; m++) oP[c][m] = make_float2(0.0f, 0.0f);

        // ---- experts (rolled loop: fits I$) ----
        #pragma unroll 1
        for (int e = 0; e < ED; e++) {
            const uint4 bh4 = *(const uint4*)(sB1frag + ((e * 2 + 0) * 32 + lane) * 16);
            const uint4 bl4 = *(const uint4*)(sB1frag + ((e * 2 + 1) * 32 + lane) * 16);
            uint4 cH[4], cL[4];
            #pragma unroll
            for (int c4 = 0; c4 < 4; c4++) {
                cH[c4] = *(const uint4*)(sBfrag + ((e * 8 + c4    ) * 32 + lane) * 16);
                cL[c4] = *(const uint4*)(sBfrag + ((e * 8 + c4 + 4) * 32 + lane) * 16);
            }
            float2 b2p[4]; float4 w34[4];
            #pragma unroll
            for (int nf = 0; nf < 4; nf++) {
                b2p[nf] = *(const float2*)&sb2[e * HH + nf * 8 + 2 * q];
                w34[nf] = *(const float4*)&sW3[(e * HH + nf * 8 + 2 * q) * DO];
            }
            const float y0b = sb3[e * DO + 0];
            const float y1b = sb3[e * DO + 1];

            #pragma unroll
            for (int c = 0; c < 2; c++) {
                // layer 1: k16 MMA ([xhi|xlo] . [whi|whi], C=0) + k8 MMA (xhi . wlo)
                float h1d[2][4][4];
                #pragma unroll
                for (int nf = 0; nf < 4; nf++) {
                    const u32 bh = (nf == 0) ? bh4.x : (nf == 1) ? bh4.y : (nf == 2) ? bh4.z : bh4.w;
                    const u32 bl = (nf == 0) ? bl4.x : (nf == 1) ? bl4.y : (nf == 2) ? bl4.z : bl4.w;
                    #pragma unroll
                    for (int mf = 0; mf < 2; mf++) {
                        mma_bf16_c(h1d[mf][nf][0], h1d[mf][nf][1], h1d[mf][nf][2], h1d[mf][nf][3],
                                   xhi[c][mf][0], xhi[c][mf][1], xlo[c][mf][0], xlo[c][mf][1],
                                   bh, bh, fz, fz, fz, fz);
                        mma_bf16_k8(h1d[mf][nf][0], h1d[mf][nf][1], h1d[mf][nf][2], h1d[mf][nf][3],
                                    xhi[c][mf][0], xhi[c][mf][1], bl);
                    }
                }

                // relu + bf16 split -> layer-2 A-frags
                u32 ahi[2][2][4], alo[2][2][4];
                #pragma unroll
                for (int mf = 0; mf < 2; mf++) {
                    #pragma unroll
                    for (int kf = 0; kf < 2; kf++) {
                        #pragma unroll
                        for (int half = 0; half < 2; half++) {
                            const int nf = 2 * kf + half;
                            const float f0 = fmaxf(h1d[mf][nf][0], 0.0f);
                            const float f1 = fmaxf(h1d[mf][nf][1], 0.0f);
                            const float f2 = fmaxf(h1d[mf][nf][2], 0.0f);
                            const float f3 = fmaxf(h1d[mf][nf][3], 0.0f);
                            const u32 hA = bf16x2_of(f0, f1);
                            const u32 hB = bf16x2_of(f2, f3);
                            ahi[mf][kf][half * 2 + 0] = hA;
                            ahi[mf][kf][half * 2 + 1] = hB;
                            alo[mf][kf][half * 2 + 0] = bf16x2_of(f0 - bflo(hA), f1 - bfhi(hA));
                            alo[mf][kf][half * 2 + 1] = bf16x2_of(f2 - bflo(hB), f3 - bfhi(hB));
                        }
                    }
                }

                // layer-2: D = A_hi*B_hi + A_lo*B_hi + A_hi*B_lo, C(first) = b2
                float dd[2][4][4];
                #pragma unroll
                for (int nf = 0; nf < 4; nf++) {
                    const uint4 h40 = cH[0 * 2 + (nf >> 1)];
                    const uint4 l40 = cL[0 * 2 + (nf >> 1)];
                    const uint4 h41 = cH[1 * 2 + (nf >> 1)];
                    const uint4 l41 = cL[1 * 2 + (nf >> 1)];
                    const u32 b0h0 = (nf & 1) ? h40.z : h40.x;
                    const u32 b1h0 = (nf & 1) ? h40.w : h40.y;
                    const u32 b0l0 = (nf & 1) ? l40.z : l40.x;
                    const u32 b1l0 = (nf & 1) ? l40.w : l40.y;
                    const u32 b0h1 = (nf & 1) ? h41.z : h41.x;
                    const u32 b1h1 = (nf & 1) ? h41.w : h41.y;
                    const u32 b0l1 = (nf & 1) ? l41.z : l41.x;
                    const u32 b1l1 = (nf & 1) ? l41.w : l41.y;
                    #pragma unroll
                    for (int mf = 0; mf < 2; mf++) {
                        mma_bf16_c(dd[mf][nf][0], dd[mf][nf][1], dd[mf][nf][2], dd[mf][nf][3],
                                   ahi[mf][0][0], ahi[mf][0][1], ahi[mf][0][2], ahi[mf][0][3],
                                   b0h0, b1h0,
                                   b2p[nf].x, b2p[nf].y, b2p[nf].x, b2p[nf].y);
                        mma_bf16(dd[mf][nf][0], dd[mf][nf][1], dd[mf][nf][2], dd[mf][nf][3],
                                 alo[mf][0][0], alo[mf][0][1], alo[mf][0][2], alo[mf][0][3],
                                 b0h0, b1h0);
                        mma_bf16(dd[mf][nf][0], dd[mf][nf][1], dd[mf][nf][2], dd[mf][nf][3],
                                 ahi[mf][0][0], ahi[mf][0][1], ahi[mf][0][2], ahi[mf][0][3],
                                 b0l0, b1l0);
                        mma_bf16(dd[mf][nf][0], dd[mf][nf][1], dd[mf][nf][2], dd[mf][nf][3],
                                 ahi[mf][1][0], ahi[mf][1][1], ahi[mf][1][2], ahi[mf][1][3],
                                 b0h1, b1h1);
                        mma_bf16(dd[mf][nf][0], dd[mf][nf][1], dd[mf][nf][2], dd[mf][nf][3],
                                 alo[mf][1][0], alo[mf][1][1], alo[mf][1][2], alo[mf][1][3],
                                 b0h1, b1h1);
                        mma_bf16(dd[mf][nf][0], dd[mf][nf][1], dd[mf][nf][2], dd[mf][nf][3],
                                 ahi[mf][1][0], ahi[mf][1][1], ahi[mf][1][2], ahi[mf][1][3],
                                 b0l1, b1l1);
                    }
                }

                // epilogue: relu + layer3 + gate (from smem) accumulate
                #pragma unroll
                for (int m = 0; m < 4; m++) {
                    const int mf = m >> 1, r = m & 1;
                    float y0 = y0b, y1 = y1b;
                    #pragma unroll
                    for (int nf = 0; nf < 4; nf++) {
                        const float ha = fmaxf(dd[mf][nf][r * 2 + 0], 0.0f);
                        const float hb = fmaxf(dd[mf][nf][r * 2 + 1], 0.0f);
                        y0 = fmaf(ha, w34[nf].x, y0);
                        y1 = fmaf(ha, w34[nf].y, y1);
                        y0 = fmaf(hb, w34[nf].z, y0);
                        y1 = fmaf(hb, w34[nf].w, y1);
                    }
                    const float ge = sgw[e * 64 + 32 * c + 8 * m + g];
                    oP[c][m].x = fmaf(ge, y0, oP[c][m].x);
                    oP[c][m].y = fmaf(ge, y1, oP[c][m].y);
                }
            }
        }

        // ---- per-chunk quad butterfly reduction + store ----
        #pragma unroll
        for (int c = 0; c < 2; c++) {
            #pragma unroll
            for (int m = 0; m < 4; m++) {
                #pragma unroll
                for (int o = 1; o <= 2; o <<= 1) {
                    oP[c][m].x += __shfl_xor_sync(0xffffffffu, oP[c][m].x, o);
                    oP[c][m].y += __shfl_xor_sync(0xffffffffu, oP[c][m].y, o);
                }
            }
            float2 res = oP[c][0];
            if (q == 1) res = oP[c][1];
            if (q == 2) res = oP[c][2];
            if (q == 3) res = oP[c][3];
            const int t = base + 32 * c + g + 8 * q;
            if (t < B) ((float2*)gout)[t] = res;
        }
    }
}

extern "C" void kernel_launch(void* const* d_in, const int* in_sizes, int n_in,
                              void* d_out, int out_size)
{
    const float* x   = (const float*)d_in[0];
    const float* W1  = (const float*)d_in[1];
    const float* b1  = (const float*)d_in[2];
    const float* W2  = (const float*)d_in[3];
    const float* b2  = (const float*)d_in[4];
    const float* W3  = (const float*)d_in[5];
    const float* b3  = (const float*)d_in[6];
    const float* Wg1 = (const float*)d_in[7];
    const float* bg1 = (const float*)d_in[8];
    const float* Wg2 = (const float*)d_in[9];
    const float* bg2 = (const float*)d_in[10];
    float* out = (float*)d_out;

    const int B  = in_sizes[0] / DI;
    const int NT = (B + 255) / 256;

    int nsm = 148;
    cudaDeviceGetAttribute(&nsm, cudaDevAttrMultiProcessorCount, 0);
    int grid = 2 * nsm;
    if (grid > NT) grid = NT;

    moe_mma_kernel<<<grid, 128>>>(x, W1, b1, W2, b2, W3, b3,
                                  Wg1, bg1, Wg2, bg2, out, B, NT);
}